// round 1
// baseline (speedup 1.0000x reference)
#include <cuda_runtime.h>
#include <math.h>

// Problem constants
#define Bb 4
#define Tt 2048
#define Cc 1024
#define Hh 16
#define Dd 64
#define Mm (Bb*Tt)          // 8192 rows
#define N_QKV (3*Cc)        // 3072
#define SCALE 0.125f        // 1/sqrt(64)

// Scratch (device globals: allocation-free per harness rules)
__device__ float g_Q[(size_t)Bb*Hh*Tt*Dd];   // [B,H,T,D]
__device__ float g_K[(size_t)Bb*Hh*Tt*Dd];
__device__ float g_V[(size_t)Bb*Hh*Tt*Dd];
__device__ float g_Y[(size_t)Mm*Cc];         // [B,T,C] attention output

// ---------------------------------------------------------------------------
// SGEMM: C[M,N] = A[M,K] @ W[K,N] + bias[N]
// BM=BN=128, BK=8, 256 threads, 8x8 per-thread micro-tile.
// MODE 0: epilogue scatters into g_Q/g_K/g_V ([B,H,T,D]); MODE 1: plain store.
// All dims divisible by tile sizes -> no bounds checks.
// ---------------------------------------------------------------------------
template<int MODE>
__global__ __launch_bounds__(256)
void sgemm_kernel(const float* __restrict__ A, const float* __restrict__ W,
                  const float* __restrict__ bias, float* __restrict__ C,
                  int Kdim, int Ndim)
{
    __shared__ float As[8][128];
    __shared__ float Bs[8][128];

    const int cRow = blockIdx.y;
    const int cCol = blockIdx.x;
    const int tid  = threadIdx.x;
    const int threadCol = tid & 15;   // 0..15
    const int threadRow = tid >> 4;   // 0..15

    const float* Ap = A + (size_t)cRow * 128 * Kdim;
    const float* Wp = W + (size_t)cCol * 128;

    const int aRow = tid >> 1;          // 0..127
    const int aCol = (tid & 1) * 4;     // 0 or 4
    const int bRow = tid >> 5;          // 0..7
    const int bCol = (tid & 31) * 4;    // 0..124

    float tm[8][8] = {};
    float regM[8], regN[8];

    for (int kt = 0; kt < Kdim; kt += 8) {
        float4 a4 = *(const float4*)(Ap + (size_t)aRow * Kdim + kt + aCol);
        As[aCol+0][aRow] = a4.x;
        As[aCol+1][aRow] = a4.y;
        As[aCol+2][aRow] = a4.z;
        As[aCol+3][aRow] = a4.w;
        float4 b4 = *(const float4*)(Wp + (size_t)(kt + bRow) * Ndim + bCol);
        *(float4*)(&Bs[bRow][bCol]) = b4;
        __syncthreads();

        #pragma unroll
        for (int k = 0; k < 8; k++) {
            #pragma unroll
            for (int i = 0; i < 8; i += 4) {
                float4 t = *(const float4*)(&As[k][threadRow*8 + i]);
                regM[i+0]=t.x; regM[i+1]=t.y; regM[i+2]=t.z; regM[i+3]=t.w;
            }
            #pragma unroll
            for (int j = 0; j < 8; j += 4) {
                float4 t = *(const float4*)(&Bs[k][threadCol*8 + j]);
                regN[j+0]=t.x; regN[j+1]=t.y; regN[j+2]=t.z; regN[j+3]=t.w;
            }
            #pragma unroll
            for (int i = 0; i < 8; i++)
                #pragma unroll
                for (int j = 0; j < 8; j++)
                    tm[i][j] = fmaf(regM[i], regN[j], tm[i][j]);
        }
        __syncthreads();
    }

    const int rowBase = cRow * 128 + threadRow * 8;
    const int colBase = cCol * 128 + threadCol * 8;

    #pragma unroll
    for (int i = 0; i < 8; i++) {
        const int m = rowBase + i;
        #pragma unroll
        for (int j0 = 0; j0 < 8; j0 += 4) {
            const int n = colBase + j0;
            float4 bb = *(const float4*)(bias + n);
            float4 v = make_float4(tm[i][j0+0] + bb.x, tm[i][j0+1] + bb.y,
                                   tm[i][j0+2] + bb.z, tm[i][j0+3] + bb.w);
            if (MODE == 0) {
                // scatter into Q/K/V [B,H,T,D]
                const int b = m >> 11;          // /T
                const int t = m & (Tt - 1);
                const int s = n >> 10;          // /C : 0=Q 1=K 2=V
                const int c = n & (Cc - 1);
                const int h = c >> 6;           // /D
                const int d = c & 63;
                float* dst = (s == 0) ? g_Q : (s == 1) ? g_K : g_V;
                *(float4*)(dst + (((size_t)(b*Hh + h) * Tt + t) * Dd + d)) = v;
            } else {
                *(float4*)(C + (size_t)m * Ndim + n) = v;
            }
        }
    }
}

// ---------------------------------------------------------------------------
// Flash attention (causal): per block = (qtile of 64, head, batch).
// 256 threads, BQ=BKV=64, D=64.  4x4 micro-tiles for S=QK^T and O+=P@V.
// Online softmax; row stats via 4-threads-per-row smem reduction.
// ---------------------------------------------------------------------------
#define LDp 65   // smem row pitch (pad to kill bank conflicts)

__global__ __launch_bounds__(256)
void attn_kernel()
{
    extern __shared__ float sm[];
    float* Qs   = sm;                   // 64*65
    float* Ks   = Qs + 64*LDp;
    float* Vs   = Ks + 64*LDp;
    float* Ss   = Vs + 64*LDp;
    float* mrow = Ss + 64*LDp;          // 64
    float* lrow = mrow + 64;            // 64
    float* corr = lrow + 64;            // 64
    float* red  = corr + 64;            // 64*4

    const int qb = blockIdx.x;
    const int h  = blockIdx.y;
    const int b  = blockIdx.z;
    const int tid = threadIdx.x;
    const int ty = tid >> 4;            // 0..15
    const int tx = tid & 15;            // 0..15
    const int r  = tid >> 2;            // 0..63  (softmax row)
    const int g  = tid & 3;             // 0..3   (softmax group)

    const size_t headBase = ((size_t)(b*Hh + h) * Tt) * Dd;
    const float* Qg = g_Q + headBase + (size_t)qb * 64 * Dd;

    // Load Q tile (stays resident)
    #pragma unroll
    for (int r4 = 0; r4 < 4; r4++) {
        int f   = tid + r4 * 256;       // float4 index 0..1023
        int row = f >> 4;
        int col = (f & 15) * 4;
        float4 q4 = *(const float4*)(Qg + row * Dd + col);
        Qs[row*LDp+col+0]=q4.x; Qs[row*LDp+col+1]=q4.y;
        Qs[row*LDp+col+2]=q4.z; Qs[row*LDp+col+3]=q4.w;
    }
    if (tid < 64) { mrow[tid] = -1e30f; lrow[tid] = 0.f; }

    float o[4][4] = {};
    __syncthreads();

    for (int kb = 0; kb <= qb; kb++) {
        const float* Kg = g_K + headBase + (size_t)kb * 64 * Dd;
        const float* Vg = g_V + headBase + (size_t)kb * 64 * Dd;
        #pragma unroll
        for (int r4 = 0; r4 < 4; r4++) {
            int f   = tid + r4 * 256;
            int row = f >> 4;
            int col = (f & 15) * 4;
            float4 k4 = *(const float4*)(Kg + row * Dd + col);
            Ks[row*LDp+col+0]=k4.x; Ks[row*LDp+col+1]=k4.y;
            Ks[row*LDp+col+2]=k4.z; Ks[row*LDp+col+3]=k4.w;
            float4 v4 = *(const float4*)(Vg + row * Dd + col);
            Vs[row*LDp+col+0]=v4.x; Vs[row*LDp+col+1]=v4.y;
            Vs[row*LDp+col+2]=v4.z; Vs[row*LDp+col+3]=v4.w;
        }
        __syncthreads();

        // S tile: s[i][j] = Q[ty*4+i,:] . K[tx*4+j,:]
        float s[4][4] = {};
        #pragma unroll 8
        for (int d = 0; d < 64; d++) {
            float qf[4], kf[4];
            #pragma unroll
            for (int i = 0; i < 4; i++) qf[i] = Qs[(ty*4+i)*LDp + d];
            #pragma unroll
            for (int j = 0; j < 4; j++) kf[j] = Ks[(tx*4+j)*LDp + d];
            #pragma unroll
            for (int i = 0; i < 4; i++)
                #pragma unroll
                for (int j = 0; j < 4; j++)
                    s[i][j] = fmaf(qf[i], kf[j], s[i][j]);
        }

        const bool diag = (kb == qb);
        #pragma unroll
        for (int i = 0; i < 4; i++)
            #pragma unroll
            for (int j = 0; j < 4; j++) {
                float v = s[i][j] * SCALE;
                if (diag && (tx*4 + j) > (ty*4 + i)) v = -1e30f;
                Ss[(ty*4+i)*LDp + (tx*4+j)] = v;
            }
        __syncthreads();

        // Online softmax row stats: 4 threads per row, 16 cols each
        float pm = -1e30f;
        #pragma unroll
        for (int c = 0; c < 16; c++) pm = fmaxf(pm, Ss[r*LDp + g*16 + c]);
        red[r*4 + g] = pm;
        __syncthreads();
        if (g == 0) {
            float mt = fmaxf(fmaxf(red[r*4], red[r*4+1]), fmaxf(red[r*4+2], red[r*4+3]));
            float mold = mrow[r];
            float mnew = fmaxf(mold, mt);
            corr[r] = __expf(mold - mnew);
            mrow[r] = mnew;
        }
        __syncthreads();
        const float mnew = mrow[r];
        float ps = 0.f;
        #pragma unroll
        for (int c = 0; c < 16; c++) {
            float p = __expf(Ss[r*LDp + g*16 + c] - mnew);
            Ss[r*LDp + g*16 + c] = p;
            ps += p;
        }
        red[r*4 + g] = ps;
        __syncthreads();                 // also publishes P in Ss
        if (g == 0)
            lrow[r] = lrow[r] * corr[r] + red[r*4] + red[r*4+1] + red[r*4+2] + red[r*4+3];

        // O update: o[i][j] over (q=ty*4+i, d=tx*4+j)
        #pragma unroll
        for (int i = 0; i < 4; i++) {
            const float cf = corr[ty*4 + i];
            #pragma unroll
            for (int j = 0; j < 4; j++) o[i][j] *= cf;
        }
        #pragma unroll 8
        for (int k = 0; k < 64; k++) {
            float pf[4], vf[4];
            #pragma unroll
            for (int i = 0; i < 4; i++) pf[i] = Ss[(ty*4+i)*LDp + k];
            #pragma unroll
            for (int j = 0; j < 4; j++) vf[j] = Vs[k*LDp + tx*4 + j];
            #pragma unroll
            for (int i = 0; i < 4; i++)
                #pragma unroll
                for (int j = 0; j < 4; j++)
                    o[i][j] = fmaf(pf[i], vf[j], o[i][j]);
        }
        __syncthreads();                 // protect Ks/Vs/Ss/lrow before next tile
    }

    // Finalize and store to Y [B,T,C] at column h*64
    float* Yp = g_Y + ((size_t)b * Tt + (size_t)qb * 64) * Cc + h * 64;
    #pragma unroll
    for (int i = 0; i < 4; i++) {
        const float inv = 1.f / lrow[ty*4 + i];
        float4 v = make_float4(o[i][0]*inv, o[i][1]*inv, o[i][2]*inv, o[i][3]*inv);
        *(float4*)(Yp + (size_t)(ty*4 + i) * Cc + tx * 4) = v;
    }
}

// ---------------------------------------------------------------------------
extern "C" void kernel_launch(void* const* d_in, const int* in_sizes, int n_in,
                              void* d_out, int out_size)
{
    const float* x      = (const float*)d_in[0];
    const float* w_attn = (const float*)d_in[1];
    const float* b_attn = (const float*)d_in[2];
    const float* w_proj = (const float*)d_in[3];
    const float* b_proj = (const float*)d_in[4];
    float* out = (float*)d_out;

    // 1) QKV GEMM: [8192,1024] @ [1024,3072], scatter into Q/K/V
    {
        dim3 grid(N_QKV / 128, Mm / 128);
        sgemm_kernel<0><<<grid, 256>>>(x, w_attn, b_attn, nullptr, Cc, N_QKV);
    }

    // 2) Flash attention
    {
        const int smem = (4 * 64 * LDp + 64 * 3 + 64 * 4) * (int)sizeof(float);
        cudaFuncSetAttribute(attn_kernel, cudaFuncAttributeMaxDynamicSharedMemorySize, smem);
        dim3 grid(Tt / 64, Hh, Bb);
        attn_kernel<<<grid, 256, smem>>>();
    }

    // 3) Output projection: [8192,1024] @ [1024,1024]
    {
        dim3 grid(Cc / 128, Mm / 128);
        float* Yp;
        cudaGetSymbolAddress((void**)&Yp, g_Y);
        sgemm_kernel<1><<<grid, 256>>>(Yp, w_proj, b_proj, out, Cc, Cc);
    }
}

// round 14
// speedup vs baseline: 1.4229x; 1.4229x over previous
#include <cuda_runtime.h>
#include <cuda_bf16.h>
#include <cstdint>
#include <math.h>

// Problem constants
#define Bb 4
#define Tt 2048
#define Cc 1024
#define Hh 16
#define Dd 64
#define Mm (Bb*Tt)          // 8192
#define N_QKV (3*Cc)        // 3072
#define SCALE 0.125f

// ---------------- device scratch ----------------
__device__ float g_Q[(size_t)Bb*Hh*Tt*Dd];
__device__ float g_K[(size_t)Bb*Hh*Tt*Dd];
__device__ float g_V[(size_t)Bb*Hh*Tt*Dd];
__device__ float g_Y[(size_t)Mm*Cc];

__device__ __nv_bfloat16 g_Ah[(size_t)Mm*Cc],  g_Al[(size_t)Mm*Cc];      // x split [M,K]
__device__ __nv_bfloat16 g_Wh[(size_t)N_QKV*Cc], g_Wl[(size_t)N_QKV*Cc]; // w_attn^T [N,K]
__device__ __nv_bfloat16 g_Ph[(size_t)Cc*Cc],  g_Pl[(size_t)Cc*Cc];      // w_proj^T [N,K]
__device__ __nv_bfloat16 g_Yh[(size_t)Mm*Cc],  g_Yl[(size_t)Mm*Cc];      // attn out split

// ---------------- mma.sync helper (bf16 x bf16 -> f32, m16n8k16) ----------------
__device__ __forceinline__ void mma16816(float* d, const uint32_t* a, const uint32_t* b) {
    asm volatile(
        "mma.sync.aligned.m16n8k16.row.col.f32.bf16.bf16.f32 "
        "{%0,%1,%2,%3}, {%4,%5,%6,%7}, {%8,%9}, {%0,%1,%2,%3};"
        : "+f"(d[0]), "+f"(d[1]), "+f"(d[2]), "+f"(d[3])
        : "r"(a[0]), "r"(a[1]), "r"(a[2]), "r"(a[3]), "r"(b[0]), "r"(b[1]));
}

// ---------------- pre-pass: split fp32 -> (hi, lo) bf16 ----------------
__global__ __launch_bounds__(256)
void conv_split(const float* __restrict__ src, __nv_bfloat16* __restrict__ hi,
                __nv_bfloat16* __restrict__ lo, int n4)
{
    int i = blockIdx.x * blockDim.x + threadIdx.x;
    if (i >= n4) return;
    float4 v = ((const float4*)src)[i];
    float vv[4] = {v.x, v.y, v.z, v.w};
    __nv_bfloat16 h[4], l[4];
    #pragma unroll
    for (int j = 0; j < 4; j++) {
        h[j] = __float2bfloat16(vv[j]);
        l[j] = __float2bfloat16(vv[j] - __bfloat162float(h[j]));
    }
    ((uint2*)hi)[i] = *(uint2*)h;
    ((uint2*)lo)[i] = *(uint2*)l;
}

// ---------------- pre-pass: transpose [K,N] -> [N,K] + split ----------------
__global__ __launch_bounds__(256)
void trans_split(const float* __restrict__ W, __nv_bfloat16* __restrict__ hi,
                 __nv_bfloat16* __restrict__ lo, int Kd, int Nd)
{
    __shared__ float tile[32][33];
    int k0 = blockIdx.y * 32, n0 = blockIdx.x * 32;
    int tx = threadIdx.x, ty = threadIdx.y;   // 32 x 8
    #pragma unroll
    for (int r = ty; r < 32; r += 8)
        tile[r][tx] = W[(size_t)(k0 + r) * Nd + n0 + tx];
    __syncthreads();
    #pragma unroll
    for (int r = ty; r < 32; r += 8) {
        float v = tile[tx][r];
        __nv_bfloat16 h = __float2bfloat16(v);
        __nv_bfloat16 l = __float2bfloat16(v - __bfloat162float(h));
        hi[(size_t)(n0 + r) * Kd + k0 + tx] = h;
        lo[(size_t)(n0 + r) * Kd + k0 + tx] = l;
    }
}

// ---------------- mma.sync bf16-split GEMM ----------------
// C[M,N] = A[M,K] @ B^T (B stored [N,K]) + bias.
// BM=128, BN=128, BK=32. 8 warps, each 32x64 (2 m-frags x 8 n-frags).
// MODE 0: scatter into g_Q/g_K/g_V;  MODE 1: plain store.
// SPAD=40: 80-byte row pitch -> float4-aligned every row; fragment-load banks
// (r*20+gt mod 32) all-distinct -> conflict-free.
#define SPAD 40

template<int MODE>
__global__ __launch_bounds__(256)
void gemm_mma(const __nv_bfloat16* __restrict__ Ahp, const __nv_bfloat16* __restrict__ Alp,
              const __nv_bfloat16* __restrict__ Bhp, const __nv_bfloat16* __restrict__ Blp,
              const float* __restrict__ bias, float* __restrict__ Cout,
              int Kdim, int Ndim)
{
    __shared__ __align__(16) __nv_bfloat16 Ah_s[128*SPAD], Al_s[128*SPAD];
    __shared__ __align__(16) __nv_bfloat16 Bh_s[128*SPAD], Bl_s[128*SPAD];

    const int tid  = threadIdx.x;
    const int wid  = tid >> 5, lane = tid & 31;
    const int warp_row = (wid & 3) * 32;
    const int warp_col = (wid >> 2) * 64;
    const int gq = lane >> 2;
    const int gt = lane & 3;

    const int mBlk = blockIdx.y, nBlk = blockIdx.x;
    const __nv_bfloat16* Ah0 = Ahp + (size_t)mBlk * 128 * Kdim;
    const __nv_bfloat16* Al0 = Alp + (size_t)mBlk * 128 * Kdim;
    const __nv_bfloat16* Bh0 = Bhp + (size_t)nBlk * 128 * Kdim;
    const __nv_bfloat16* Bl0 = Blp + (size_t)nBlk * 128 * Kdim;

    float acc[2][8][4] = {};

    const int nChunks = Kdim >> 5;
    for (int kc = 0; kc < nChunks; kc++) {
        const int kofs = kc * 32;
        #pragma unroll
        for (int it = 0; it < 2; it++) {
            int u = tid + it * 256;
            int row = u >> 2, cb = (u & 3) * 8;
            size_t gofs = (size_t)row * Kdim + kofs + cb;
            int sofs = row * SPAD + cb;
            *(float4*)&Ah_s[sofs] = *(const float4*)(Ah0 + gofs);
            *(float4*)&Al_s[sofs] = *(const float4*)(Al0 + gofs);
            *(float4*)&Bh_s[sofs] = *(const float4*)(Bh0 + gofs);
            *(float4*)&Bl_s[sofs] = *(const float4*)(Bl0 + gofs);
        }
        __syncthreads();

        #pragma unroll
        for (int ks = 0; ks < 2; ks++) {
            const int c = ks * 16 + gt * 2;
            uint32_t ah[2][4], al[2][4];
            #pragma unroll
            for (int mf = 0; mf < 2; mf++) {
                const int r = warp_row + mf * 16 + gq;
                ah[mf][0] = *(const uint32_t*)&Ah_s[r * SPAD + c];
                ah[mf][1] = *(const uint32_t*)&Ah_s[(r + 8) * SPAD + c];
                ah[mf][2] = *(const uint32_t*)&Ah_s[r * SPAD + c + 8];
                ah[mf][3] = *(const uint32_t*)&Ah_s[(r + 8) * SPAD + c + 8];
                al[mf][0] = *(const uint32_t*)&Al_s[r * SPAD + c];
                al[mf][1] = *(const uint32_t*)&Al_s[(r + 8) * SPAD + c];
                al[mf][2] = *(const uint32_t*)&Al_s[r * SPAD + c + 8];
                al[mf][3] = *(const uint32_t*)&Al_s[(r + 8) * SPAD + c + 8];
            }
            #pragma unroll
            for (int nf = 0; nf < 8; nf++) {
                const int n = warp_col + nf * 8 + gq;
                uint32_t bh[2], bl[2];
                bh[0] = *(const uint32_t*)&Bh_s[n * SPAD + c];
                bh[1] = *(const uint32_t*)&Bh_s[n * SPAD + c + 8];
                bl[0] = *(const uint32_t*)&Bl_s[n * SPAD + c];
                bl[1] = *(const uint32_t*)&Bl_s[n * SPAD + c + 8];
                #pragma unroll
                for (int mf = 0; mf < 2; mf++) {
                    mma16816(acc[mf][nf], ah[mf], bh);
                    mma16816(acc[mf][nf], ah[mf], bl);
                    mma16816(acc[mf][nf], al[mf], bh);
                }
            }
        }
        __syncthreads();
    }

    #pragma unroll
    for (int mf = 0; mf < 2; mf++) {
        #pragma unroll
        for (int nf = 0; nf < 8; nf++) {
            const int m0 = mBlk * 128 + warp_row + mf * 16 + gq;
            const int n  = nBlk * 128 + warp_col + nf * 8 + gt * 2;
            float2 bb = *(const float2*)(bias + n);
            float2 v0 = make_float2(acc[mf][nf][0] + bb.x, acc[mf][nf][1] + bb.y);
            float2 v1 = make_float2(acc[mf][nf][2] + bb.x, acc[mf][nf][3] + bb.y);
            if (MODE == 0) {
                const int s = n >> 10, cx = n & (Cc - 1);
                const int h = cx >> 6, d = cx & 63;
                float* dst = (s == 0) ? g_Q : (s == 1) ? g_K : g_V;
                const int b0 = m0 >> 11, t0 = m0 & (Tt - 1);
                *(float2*)(dst + (((size_t)(b0 * Hh + h) * Tt + t0) * Dd + d)) = v0;
                const int m1 = m0 + 8;
                const int b1 = m1 >> 11, t1 = m1 & (Tt - 1);
                *(float2*)(dst + (((size_t)(b1 * Hh + h) * Tt + t1) * Dd + d)) = v1;
            } else {
                *(float2*)(Cout + (size_t)m0 * Ndim + n) = v0;
                *(float2*)(Cout + (size_t)(m0 + 8) * Ndim + n) = v1;
            }
        }
    }
}

// ---------------- flash attention (fp32 SIMT, PROVEN in Round 1) ----------------
#define LDp 65

__global__ __launch_bounds__(256)
void attn_kernel()
{
    extern __shared__ float smf[];
    float* Qs   = smf;
    float* Ks   = Qs + 64*LDp;
    float* Vs   = Ks + 64*LDp;
    float* Ss   = Vs + 64*LDp;
    float* mrow = Ss + 64*LDp;
    float* lrow = mrow + 64;
    float* corr = lrow + 64;
    float* red  = corr + 64;

    const int qb = blockIdx.x;
    const int h  = blockIdx.y;
    const int b  = blockIdx.z;
    const int tid = threadIdx.x;
    const int ty = tid >> 4;
    const int tx = tid & 15;
    const int r  = tid >> 2;
    const int g  = tid & 3;

    const size_t headBase = ((size_t)(b*Hh + h) * Tt) * Dd;
    const float* Qg = g_Q + headBase + (size_t)qb * 64 * Dd;

    #pragma unroll
    for (int r4 = 0; r4 < 4; r4++) {
        int f   = tid + r4 * 256;
        int row = f >> 4;
        int col = (f & 15) * 4;
        float4 q4 = *(const float4*)(Qg + row * Dd + col);
        Qs[row*LDp+col+0]=q4.x; Qs[row*LDp+col+1]=q4.y;
        Qs[row*LDp+col+2]=q4.z; Qs[row*LDp+col+3]=q4.w;
    }
    if (tid < 64) { mrow[tid] = -1e30f; lrow[tid] = 0.f; }

    float o[4][4] = {};
    __syncthreads();

    for (int kb = 0; kb <= qb; kb++) {
        const float* Kg = g_K + headBase + (size_t)kb * 64 * Dd;
        const float* Vg = g_V + headBase + (size_t)kb * 64 * Dd;
        #pragma unroll
        for (int r4 = 0; r4 < 4; r4++) {
            int f   = tid + r4 * 256;
            int row = f >> 4;
            int col = (f & 15) * 4;
            float4 k4 = *(const float4*)(Kg + row * Dd + col);
            Ks[row*LDp+col+0]=k4.x; Ks[row*LDp+col+1]=k4.y;
            Ks[row*LDp+col+2]=k4.z; Ks[row*LDp+col+3]=k4.w;
            float4 v4 = *(const float4*)(Vg + row * Dd + col);
            Vs[row*LDp+col+0]=v4.x; Vs[row*LDp+col+1]=v4.y;
            Vs[row*LDp+col+2]=v4.z; Vs[row*LDp+col+3]=v4.w;
        }
        __syncthreads();

        float s[4][4] = {};
        #pragma unroll 8
        for (int d = 0; d < 64; d++) {
            float qf[4], kf[4];
            #pragma unroll
            for (int i = 0; i < 4; i++) qf[i] = Qs[(ty*4+i)*LDp + d];
            #pragma unroll
            for (int j = 0; j < 4; j++) kf[j] = Ks[(tx*4+j)*LDp + d];
            #pragma unroll
            for (int i = 0; i < 4; i++)
                #pragma unroll
                for (int j = 0; j < 4; j++)
                    s[i][j] = fmaf(qf[i], kf[j], s[i][j]);
        }

        const bool diag = (kb == qb);
        #pragma unroll
        for (int i = 0; i < 4; i++)
            #pragma unroll
            for (int j = 0; j < 4; j++) {
                float v = s[i][j] * SCALE;
                if (diag && (tx*4 + j) > (ty*4 + i)) v = -1e30f;
                Ss[(ty*4+i)*LDp + (tx*4+j)] = v;
            }
        __syncthreads();

        float pm = -1e30f;
        #pragma unroll
        for (int c = 0; c < 16; c++) pm = fmaxf(pm, Ss[r*LDp + g*16 + c]);
        red[r*4 + g] = pm;
        __syncthreads();
        if (g == 0) {
            float mt = fmaxf(fmaxf(red[r*4], red[r*4+1]), fmaxf(red[r*4+2], red[r*4+3]));
            float mold = mrow[r];
            float mnew = fmaxf(mold, mt);
            corr[r] = __expf(mold - mnew);
            mrow[r] = mnew;
        }
        __syncthreads();
        const float mnew = mrow[r];
        float ps = 0.f;
        #pragma unroll
        for (int c = 0; c < 16; c++) {
            float p = __expf(Ss[r*LDp + g*16 + c] - mnew);
            Ss[r*LDp + g*16 + c] = p;
            ps += p;
        }
        red[r*4 + g] = ps;
        __syncthreads();
        if (g == 0)
            lrow[r] = lrow[r] * corr[r] + red[r*4] + red[r*4+1] + red[r*4+2] + red[r*4+3];

        #pragma unroll
        for (int i = 0; i < 4; i++) {
            const float cf = corr[ty*4 + i];
            #pragma unroll
            for (int j = 0; j < 4; j++) o[i][j] *= cf;
        }
        #pragma unroll 8
        for (int k = 0; k < 64; k++) {
            float pf[4], vf[4];
            #pragma unroll
            for (int i = 0; i < 4; i++) pf[i] = Ss[(ty*4+i)*LDp + k];
            #pragma unroll
            for (int j = 0; j < 4; j++) vf[j] = Vs[k*LDp + tx*4 + j];
            #pragma unroll
            for (int i = 0; i < 4; i++)
                #pragma unroll
                for (int j = 0; j < 4; j++)
                    o[i][j] = fmaf(pf[i], vf[j], o[i][j]);
        }
        __syncthreads();
    }

    float* Yp = g_Y + ((size_t)b * Tt + (size_t)qb * 64) * Cc + h * 64;
    #pragma unroll
    for (int i = 0; i < 4; i++) {
        const float inv = 1.f / lrow[ty*4 + i];
        float4 v = make_float4(o[i][0]*inv, o[i][1]*inv, o[i][2]*inv, o[i][3]*inv);
        *(float4*)(Yp + (size_t)(ty*4 + i) * Cc + tx * 4) = v;
    }
}

// ---------------------------------------------------------------------------
extern "C" void kernel_launch(void* const* d_in, const int* in_sizes, int n_in,
                              void* d_out, int out_size)
{
    const float* x      = (const float*)d_in[0];
    const float* w_attn = (const float*)d_in[1];
    const float* b_attn = (const float*)d_in[2];
    const float* w_proj = (const float*)d_in[3];
    const float* b_proj = (const float*)d_in[4];
    float* out = (float*)d_out;

    __nv_bfloat16 *Ah, *Al, *Wh, *Wl, *Ph, *Pl, *Yh, *Yl;
    float *Yp;
    cudaGetSymbolAddress((void**)&Ah, g_Ah);  cudaGetSymbolAddress((void**)&Al, g_Al);
    cudaGetSymbolAddress((void**)&Wh, g_Wh);  cudaGetSymbolAddress((void**)&Wl, g_Wl);
    cudaGetSymbolAddress((void**)&Ph, g_Ph);  cudaGetSymbolAddress((void**)&Pl, g_Pl);
    cudaGetSymbolAddress((void**)&Yh, g_Yh);  cudaGetSymbolAddress((void**)&Yl, g_Yl);
    cudaGetSymbolAddress((void**)&Yp, g_Y);

    // No static guards: set attribute unconditionally each call.
    const int asmem = (4 * 64 * LDp + 64 * 3 + 64 * 4) * (int)sizeof(float);
    cudaFuncSetAttribute(attn_kernel, cudaFuncAttributeMaxDynamicSharedMemorySize, asmem);

    // pre-pass: split x, transpose+split weights
    conv_split<<<(Mm * Cc / 4 + 255) / 256, 256>>>(x, Ah, Al, Mm * Cc / 4);
    {
        dim3 g(N_QKV / 32, Cc / 32); dim3 blk(32, 8);
        trans_split<<<g, blk>>>(w_attn, Wh, Wl, Cc, N_QKV);
    }
    {
        dim3 g(Cc / 32, Cc / 32); dim3 blk(32, 8);
        trans_split<<<g, blk>>>(w_proj, Ph, Pl, Cc, Cc);
    }

    // QKV GEMM (tensor cores) -> scatter Q/K/V
    {
        dim3 grid(N_QKV / 128, Mm / 128);
        gemm_mma<0><<<grid, 256>>>(Ah, Al, Wh, Wl, b_attn, nullptr, Cc, N_QKV);
    }

    // flash attention (proven fp32) -> g_Y
    {
        dim3 grid(Tt / 64, Hh, Bb);
        attn_kernel<<<grid, 256, asmem>>>();
    }

    // split Y, then projection GEMM (tensor cores)
    conv_split<<<(Mm * Cc / 4 + 255) / 256, 256>>>(Yp, Yh, Yl, Mm * Cc / 4);
    {
        dim3 grid(Cc / 128, Mm / 128);
        gemm_mma<1><<<grid, 256>>>(Yh, Yl, Ph, Pl, b_proj, out, Cc, Cc);
    }
}

// round 17
// speedup vs baseline: 2.4039x; 1.6895x over previous
#include <cuda_runtime.h>
#include <cuda_bf16.h>
#include <cstdint>
#include <math.h>

// Problem constants
#define Bb 4
#define Tt 2048
#define Cc 1024
#define Hh 16
#define Dd 64
#define Mm (Bb*Tt)          // 8192
#define N_QKV (3*Cc)        // 3072
#define SCALE 0.125f

// ---------------- device scratch ----------------
__device__ float g_Q[(size_t)Bb*Hh*Tt*Dd];
__device__ float g_K[(size_t)Bb*Hh*Tt*Dd];
__device__ float g_V[(size_t)Bb*Hh*Tt*Dd];

__device__ __nv_bfloat16 g_Ah[(size_t)Mm*Cc],  g_Al[(size_t)Mm*Cc];      // x split [M,K]
__device__ __nv_bfloat16 g_Wh[(size_t)N_QKV*Cc], g_Wl[(size_t)N_QKV*Cc]; // w_attn^T [N,K]
__device__ __nv_bfloat16 g_Ph[(size_t)Cc*Cc],  g_Pl[(size_t)Cc*Cc];      // w_proj^T [N,K]
__device__ __nv_bfloat16 g_Yh[(size_t)Mm*Cc],  g_Yl[(size_t)Mm*Cc];      // attn out split

// ---------------- mma.sync helper (bf16 x bf16 -> f32, m16n8k16) ----------------
__device__ __forceinline__ void mma16816(float* d, const uint32_t* a, const uint32_t* b) {
    asm volatile(
        "mma.sync.aligned.m16n8k16.row.col.f32.bf16.bf16.f32 "
        "{%0,%1,%2,%3}, {%4,%5,%6,%7}, {%8,%9}, {%0,%1,%2,%3};"
        : "+f"(d[0]), "+f"(d[1]), "+f"(d[2]), "+f"(d[3])
        : "r"(a[0]), "r"(a[1]), "r"(a[2]), "r"(a[3]), "r"(b[0]), "r"(b[1]));
}

__device__ __forceinline__ uint32_t pack2(__nv_bfloat16 lo, __nv_bfloat16 hi) {
    return ((uint32_t)__bfloat16_as_ushort(hi) << 16) | (uint32_t)__bfloat16_as_ushort(lo);
}
__device__ __forceinline__ void split2(float a, float b, uint32_t& h, uint32_t& l) {
    __nv_bfloat16 ha = __float2bfloat16(a), hb = __float2bfloat16(b);
    __nv_bfloat16 la = __float2bfloat16(a - __bfloat162float(ha));
    __nv_bfloat16 lb = __float2bfloat16(b - __bfloat162float(hb));
    h = pack2(ha, hb);
    l = pack2(la, lb);
}

// ---------------- pre-pass: split fp32 -> (hi, lo) bf16 ----------------
__global__ __launch_bounds__(256)
void conv_split(const float* __restrict__ src, __nv_bfloat16* __restrict__ hi,
                __nv_bfloat16* __restrict__ lo, int n4)
{
    int i = blockIdx.x * blockDim.x + threadIdx.x;
    if (i >= n4) return;
    float4 v = ((const float4*)src)[i];
    float vv[4] = {v.x, v.y, v.z, v.w};
    __nv_bfloat16 h[4], l[4];
    #pragma unroll
    for (int j = 0; j < 4; j++) {
        h[j] = __float2bfloat16(vv[j]);
        l[j] = __float2bfloat16(vv[j] - __bfloat162float(h[j]));
    }
    ((uint2*)hi)[i] = *(uint2*)h;
    ((uint2*)lo)[i] = *(uint2*)l;
}

// ---------------- pre-pass: transpose [K,N] -> [N,K] + split ----------------
__global__ __launch_bounds__(256)
void trans_split(const float* __restrict__ W, __nv_bfloat16* __restrict__ hi,
                 __nv_bfloat16* __restrict__ lo, int Kd, int Nd)
{
    __shared__ float tile[32][33];
    int k0 = blockIdx.y * 32, n0 = blockIdx.x * 32;
    int tx = threadIdx.x, ty = threadIdx.y;   // 32 x 8
    #pragma unroll
    for (int r = ty; r < 32; r += 8)
        tile[r][tx] = W[(size_t)(k0 + r) * Nd + n0 + tx];
    __syncthreads();
    #pragma unroll
    for (int r = ty; r < 32; r += 8) {
        float v = tile[tx][r];
        __nv_bfloat16 h = __float2bfloat16(v);
        __nv_bfloat16 l = __float2bfloat16(v - __bfloat162float(h));
        hi[(size_t)(n0 + r) * Kd + k0 + tx] = h;
        lo[(size_t)(n0 + r) * Kd + k0 + tx] = l;
    }
}

// ---------------- mma.sync bf16-split GEMM (VALIDATED R14) ----------------
// C[M,N] = A[M,K] @ B^T (B stored [N,K]) + bias.
// __launch_bounds__(256,2): cap regs at 128 -> 2 CTAs/SM (was 129 regs, 1 CTA/SM).
#define SPAD 40

template<int MODE>
__global__ __launch_bounds__(256, 2)
void gemm_mma(const __nv_bfloat16* __restrict__ Ahp, const __nv_bfloat16* __restrict__ Alp,
              const __nv_bfloat16* __restrict__ Bhp, const __nv_bfloat16* __restrict__ Blp,
              const float* __restrict__ bias, float* __restrict__ Cout,
              int Kdim, int Ndim)
{
    __shared__ __align__(16) __nv_bfloat16 Ah_s[128*SPAD], Al_s[128*SPAD];
    __shared__ __align__(16) __nv_bfloat16 Bh_s[128*SPAD], Bl_s[128*SPAD];

    const int tid  = threadIdx.x;
    const int wid  = tid >> 5, lane = tid & 31;
    const int warp_row = (wid & 3) * 32;
    const int warp_col = (wid >> 2) * 64;
    const int gq = lane >> 2;
    const int gt = lane & 3;

    const int mBlk = blockIdx.y, nBlk = blockIdx.x;
    const __nv_bfloat16* Ah0 = Ahp + (size_t)mBlk * 128 * Kdim;
    const __nv_bfloat16* Al0 = Alp + (size_t)mBlk * 128 * Kdim;
    const __nv_bfloat16* Bh0 = Bhp + (size_t)nBlk * 128 * Kdim;
    const __nv_bfloat16* Bl0 = Blp + (size_t)nBlk * 128 * Kdim;

    float acc[2][8][4] = {};

    const int nChunks = Kdim >> 5;
    for (int kc = 0; kc < nChunks; kc++) {
        const int kofs = kc * 32;
        #pragma unroll
        for (int it = 0; it < 2; it++) {
            int u = tid + it * 256;
            int row = u >> 2, cb = (u & 3) * 8;
            size_t gofs = (size_t)row * Kdim + kofs + cb;
            int sofs = row * SPAD + cb;
            *(float4*)&Ah_s[sofs] = *(const float4*)(Ah0 + gofs);
            *(float4*)&Al_s[sofs] = *(const float4*)(Al0 + gofs);
            *(float4*)&Bh_s[sofs] = *(const float4*)(Bh0 + gofs);
            *(float4*)&Bl_s[sofs] = *(const float4*)(Bl0 + gofs);
        }
        __syncthreads();

        #pragma unroll
        for (int ks = 0; ks < 2; ks++) {
            const int c = ks * 16 + gt * 2;
            uint32_t ah[2][4], al[2][4];
            #pragma unroll
            for (int mf = 0; mf < 2; mf++) {
                const int r = warp_row + mf * 16 + gq;
                ah[mf][0] = *(const uint32_t*)&Ah_s[r * SPAD + c];
                ah[mf][1] = *(const uint32_t*)&Ah_s[(r + 8) * SPAD + c];
                ah[mf][2] = *(const uint32_t*)&Ah_s[r * SPAD + c + 8];
                ah[mf][3] = *(const uint32_t*)&Ah_s[(r + 8) * SPAD + c + 8];
                al[mf][0] = *(const uint32_t*)&Al_s[r * SPAD + c];
                al[mf][1] = *(const uint32_t*)&Al_s[(r + 8) * SPAD + c];
                al[mf][2] = *(const uint32_t*)&Al_s[r * SPAD + c + 8];
                al[mf][3] = *(const uint32_t*)&Al_s[(r + 8) * SPAD + c + 8];
            }
            #pragma unroll
            for (int nf = 0; nf < 8; nf++) {
                const int n = warp_col + nf * 8 + gq;
                uint32_t bh[2], bl[2];
                bh[0] = *(const uint32_t*)&Bh_s[n * SPAD + c];
                bh[1] = *(const uint32_t*)&Bh_s[n * SPAD + c + 8];
                bl[0] = *(const uint32_t*)&Bl_s[n * SPAD + c];
                bl[1] = *(const uint32_t*)&Bl_s[n * SPAD + c + 8];
                #pragma unroll
                for (int mf = 0; mf < 2; mf++) {
                    mma16816(acc[mf][nf], ah[mf], bh);
                    mma16816(acc[mf][nf], ah[mf], bl);
                    mma16816(acc[mf][nf], al[mf], bh);
                }
            }
        }
        __syncthreads();
    }

    #pragma unroll
    for (int mf = 0; mf < 2; mf++) {
        #pragma unroll
        for (int nf = 0; nf < 8; nf++) {
            const int m0 = mBlk * 128 + warp_row + mf * 16 + gq;
            const int n  = nBlk * 128 + warp_col + nf * 8 + gt * 2;
            float2 bb = *(const float2*)(bias + n);
            float2 v0 = make_float2(acc[mf][nf][0] + bb.x, acc[mf][nf][1] + bb.y);
            float2 v1 = make_float2(acc[mf][nf][2] + bb.x, acc[mf][nf][3] + bb.y);
            if (MODE == 0) {
                const int s = n >> 10, cx = n & (Cc - 1);
                const int h = cx >> 6, d = cx & 63;
                float* dst = (s == 0) ? g_Q : (s == 1) ? g_K : g_V;
                const int b0 = m0 >> 11, t0 = m0 & (Tt - 1);
                *(float2*)(dst + (((size_t)(b0 * Hh + h) * Tt + t0) * Dd + d)) = v0;
                const int m1 = m0 + 8;
                const int b1 = m1 >> 11, t1 = m1 & (Tt - 1);
                *(float2*)(dst + (((size_t)(b1 * Hh + h) * Tt + t1) * Dd + d)) = v1;
            } else {
                *(float2*)(Cout + (size_t)m0 * Ndim + n) = v0;
                *(float2*)(Cout + (size_t)(m0 + 8) * Ndim + n) = v1;
            }
        }
    }
}

// ---------------- flash attention via mma.sync (bf16 3-way split) ----------------
// FIX vs R13: epilogue uses the grid batch index b (r0 is a per-(b,h) row, so
// r0>>11 was always 0 -> all batches collided on batch 0).
#define KP 68

__global__ __launch_bounds__(256)
void attn_mma()
{
    __shared__ __align__(16) __nv_bfloat16 Kh_s[64*KP], Kl_s[64*KP];
    __shared__ __align__(16) __nv_bfloat16 Vh_s[64*KP], Vl_s[64*KP];   // [d][kv]

    const int qb = blockIdx.x;           // 0..15
    const int h  = blockIdx.y;
    const int b  = blockIdx.z;
    const int tid = threadIdx.x;
    const int w = tid >> 5, lane = tid & 31;
    const int gq = lane >> 2, gt = lane & 3;

    const size_t headBase = ((size_t)(b*Hh + h) * Tt) * Dd;
    const int r0 = qb*128 + w*16 + gq;   // token row within this (b,h): 0..2047

    // ---- load Q fragments (fp32 -> bf16 split), reused across all kv tiles ----
    uint32_t qh[4][4], ql[4][4];
    {
        const float* Qg = g_Q + headBase;
        #pragma unroll
        for (int ks = 0; ks < 4; ks++) {
            #pragma unroll
            for (int cc = 0; cc < 2; cc++) {
                #pragma unroll
                for (int rr = 0; rr < 2; rr++) {
                    const int reg = cc*2 + rr;
                    const int row = r0 + rr*8;
                    const int col = ks*16 + gt*2 + cc*8;
                    float2 qv = *(const float2*)(Qg + (size_t)row * Dd + col);
                    split2(qv.x, qv.y, qh[ks][reg], ql[ks][reg]);
                }
            }
        }
    }

    float o[8][4] = {};
    float mrow0 = -1e30f, mrow1 = -1e30f;
    float lrow0 = 0.f,    lrow1 = 0.f;

    const int ktmax = 2*qb + 1;
    for (int kt = 0; kt <= ktmax; kt++) {
        const float* Kg = g_K + headBase + (size_t)kt * 64 * Dd;
        const float* Vg = g_V + headBase + (size_t)kt * 64 * Dd;
        #pragma unroll
        for (int it = 0; it < 4; it++) {
            int u = tid + it * 256;
            int row = u >> 4, c4 = (u & 15) * 4;
            float4 k4 = *(const float4*)(Kg + (size_t)row * Dd + c4);
            uint32_t h01, l01, h23, l23;
            split2(k4.x, k4.y, h01, l01);
            split2(k4.z, k4.w, h23, l23);
            *(uint32_t*)&Kh_s[row*KP + c4]     = h01;
            *(uint32_t*)&Kh_s[row*KP + c4 + 2] = h23;
            *(uint32_t*)&Kl_s[row*KP + c4]     = l01;
            *(uint32_t*)&Kl_s[row*KP + c4 + 2] = l23;

            float4 v4 = *(const float4*)(Vg + (size_t)row * Dd + c4);
            float vv[4] = {v4.x, v4.y, v4.z, v4.w};
            #pragma unroll
            for (int j = 0; j < 4; j++) {
                __nv_bfloat16 vh = __float2bfloat16(vv[j]);
                __nv_bfloat16 vl = __float2bfloat16(vv[j] - __bfloat162float(vh));
                Vh_s[(c4 + j)*KP + row] = vh;
                Vl_s[(c4 + j)*KP + row] = vl;
            }
        }
        __syncthreads();

        // ---- S = Q K^T (3-way split) ----
        float s[8][4] = {};
        #pragma unroll
        for (int ks = 0; ks < 4; ks++) {
            const int c = ks*16 + gt*2;
            #pragma unroll
            for (int nf = 0; nf < 8; nf++) {
                const int n = nf*8 + gq;
                uint32_t bh[2], bl[2];
                bh[0] = *(const uint32_t*)&Kh_s[n*KP + c];
                bh[1] = *(const uint32_t*)&Kh_s[n*KP + c + 8];
                bl[0] = *(const uint32_t*)&Kl_s[n*KP + c];
                bl[1] = *(const uint32_t*)&Kl_s[n*KP + c + 8];
                mma16816(s[nf], qh[ks], bh);
                mma16816(s[nf], qh[ks], bl);
                mma16816(s[nf], ql[ks], bh);
            }
        }

        // ---- scale + causal mask + tile row max ----
        const int colbase = kt*64 + gt*2;
        float tmax0 = -1e30f, tmax1 = -1e30f;
        #pragma unroll
        for (int nf = 0; nf < 8; nf++) {
            const int j0 = colbase + nf*8, j1 = j0 + 1;
            s[nf][0] = (j0 > r0)     ? -1e30f : s[nf][0] * SCALE;
            s[nf][1] = (j1 > r0)     ? -1e30f : s[nf][1] * SCALE;
            s[nf][2] = (j0 > r0 + 8) ? -1e30f : s[nf][2] * SCALE;
            s[nf][3] = (j1 > r0 + 8) ? -1e30f : s[nf][3] * SCALE;
            tmax0 = fmaxf(tmax0, fmaxf(s[nf][0], s[nf][1]));
            tmax1 = fmaxf(tmax1, fmaxf(s[nf][2], s[nf][3]));
        }
        tmax0 = fmaxf(tmax0, __shfl_xor_sync(0xFFFFFFFFu, tmax0, 1));
        tmax0 = fmaxf(tmax0, __shfl_xor_sync(0xFFFFFFFFu, tmax0, 2));
        tmax1 = fmaxf(tmax1, __shfl_xor_sync(0xFFFFFFFFu, tmax1, 1));
        tmax1 = fmaxf(tmax1, __shfl_xor_sync(0xFFFFFFFFu, tmax1, 2));

        const float mnew0 = fmaxf(mrow0, tmax0);
        const float mnew1 = fmaxf(mrow1, tmax1);
        const float corr0 = __expf(mrow0 - mnew0);
        const float corr1 = __expf(mrow1 - mnew1);
        mrow0 = mnew0; mrow1 = mnew1;

        float sum0 = 0.f, sum1 = 0.f;
        #pragma unroll
        for (int nf = 0; nf < 8; nf++) {
            s[nf][0] = __expf(s[nf][0] - mnew0);
            s[nf][1] = __expf(s[nf][1] - mnew0);
            s[nf][2] = __expf(s[nf][2] - mnew1);
            s[nf][3] = __expf(s[nf][3] - mnew1);
            sum0 += s[nf][0] + s[nf][1];
            sum1 += s[nf][2] + s[nf][3];
        }
        sum0 += __shfl_xor_sync(0xFFFFFFFFu, sum0, 1);
        sum0 += __shfl_xor_sync(0xFFFFFFFFu, sum0, 2);
        sum1 += __shfl_xor_sync(0xFFFFFFFFu, sum1, 1);
        sum1 += __shfl_xor_sync(0xFFFFFFFFu, sum1, 2);
        lrow0 = lrow0 * corr0 + sum0;
        lrow1 = lrow1 * corr1 + sum1;

        #pragma unroll
        for (int nf = 0; nf < 8; nf++) {
            o[nf][0] *= corr0; o[nf][1] *= corr0;
            o[nf][2] *= corr1; o[nf][3] *= corr1;
        }

        // ---- O += P V (3-way split); P's D-layout == A-layout over frag pairs ----
        #pragma unroll
        for (int kc = 0; kc < 4; kc++) {
            uint32_t ph[4], pl[4];
            split2(s[2*kc][0],   s[2*kc][1],   ph[0], pl[0]);
            split2(s[2*kc][2],   s[2*kc][3],   ph[1], pl[1]);
            split2(s[2*kc+1][0], s[2*kc+1][1], ph[2], pl[2]);
            split2(s[2*kc+1][2], s[2*kc+1][3], ph[3], pl[3]);
            const int c = kc*16 + gt*2;
            #pragma unroll
            for (int nf = 0; nf < 8; nf++) {
                const int n = nf*8 + gq;
                uint32_t bh[2], bl[2];
                bh[0] = *(const uint32_t*)&Vh_s[n*KP + c];
                bh[1] = *(const uint32_t*)&Vh_s[n*KP + c + 8];
                bl[0] = *(const uint32_t*)&Vl_s[n*KP + c];
                bl[1] = *(const uint32_t*)&Vl_s[n*KP + c + 8];
                mma16816(o[nf], ph, bh);
                mma16816(o[nf], ph, bl);
                mma16816(o[nf], pl, bh);
            }
        }
        __syncthreads();
    }

    // ---- epilogue: normalize, split to bf16, store to g_Yh/g_Yl ----
    // Y row index = b*Tt + token (r0 is the token within this (b,h)).
    const float inv0 = 1.f / lrow0;
    const float inv1 = 1.f / lrow1;
    __nv_bfloat16* Yh0 = g_Yh + ((size_t)b * Tt + r0) * Cc + h*64;
    __nv_bfloat16* Yl0 = g_Yl + ((size_t)b * Tt + r0) * Cc + h*64;
    __nv_bfloat16* Yh1 = g_Yh + ((size_t)b * Tt + r0 + 8) * Cc + h*64;
    __nv_bfloat16* Yl1 = g_Yl + ((size_t)b * Tt + r0 + 8) * Cc + h*64;
    #pragma unroll
    for (int nf = 0; nf < 8; nf++) {
        const int d = nf*8 + gt*2;
        uint32_t yh, yl;
        split2(o[nf][0]*inv0, o[nf][1]*inv0, yh, yl);
        *(uint32_t*)(Yh0 + d) = yh;
        *(uint32_t*)(Yl0 + d) = yl;
        split2(o[nf][2]*inv1, o[nf][3]*inv1, yh, yl);
        *(uint32_t*)(Yh1 + d) = yh;
        *(uint32_t*)(Yl1 + d) = yl;
    }
}

// ---------------------------------------------------------------------------
extern "C" void kernel_launch(void* const* d_in, const int* in_sizes, int n_in,
                              void* d_out, int out_size)
{
    const float* x      = (const float*)d_in[0];
    const float* w_attn = (const float*)d_in[1];
    const float* b_attn = (const float*)d_in[2];
    const float* w_proj = (const float*)d_in[3];
    const float* b_proj = (const float*)d_in[4];
    float* out = (float*)d_out;

    __nv_bfloat16 *Ah, *Al, *Wh, *Wl, *Ph, *Pl, *Yh, *Yl;
    cudaGetSymbolAddress((void**)&Ah, g_Ah);  cudaGetSymbolAddress((void**)&Al, g_Al);
    cudaGetSymbolAddress((void**)&Wh, g_Wh);  cudaGetSymbolAddress((void**)&Wl, g_Wl);
    cudaGetSymbolAddress((void**)&Ph, g_Ph);  cudaGetSymbolAddress((void**)&Pl, g_Pl);
    cudaGetSymbolAddress((void**)&Yh, g_Yh);  cudaGetSymbolAddress((void**)&Yl, g_Yl);

    // pre-pass: split x, transpose+split weights
    conv_split<<<(Mm * Cc / 4 + 255) / 256, 256>>>(x, Ah, Al, Mm * Cc / 4);
    {
        dim3 g(N_QKV / 32, Cc / 32); dim3 blk(32, 8);
        trans_split<<<g, blk>>>(w_attn, Wh, Wl, Cc, N_QKV);
    }
    {
        dim3 g(Cc / 32, Cc / 32); dim3 blk(32, 8);
        trans_split<<<g, blk>>>(w_proj, Ph, Pl, Cc, Cc);
    }

    // QKV GEMM (tensor cores) -> scatter Q/K/V
    {
        dim3 grid(N_QKV / 128, Mm / 128);
        gemm_mma<0><<<grid, 256>>>(Ah, Al, Wh, Wl, b_attn, nullptr, Cc, N_QKV);
    }

    // flash attention (tensor cores) -> g_Yh/g_Yl
    {
        dim3 grid(Tt / 128, Hh, Bb);
        attn_mma<<<grid, 256>>>();
    }

    // projection GEMM (tensor cores)
    {
        dim3 grid(Cc / 128, Mm / 128);
        gemm_mma<1><<<grid, 256>>>(Yh, Yl, Ph, Pl, b_proj, out, Cc, Cc);
    }
}